// round 1
// baseline (speedup 1.0000x reference)
#include <cuda_runtime.h>

#define BATCH 2
#define SEQ   2048
#define HID   1024
#define NHEAD 16
#define HDIM  64
#define SCALE 0.125f

// Scratch (device globals — no allocations allowed)
__device__ float g_q[BATCH * NHEAD * SEQ * HDIM];
__device__ float g_k[BATCH * NHEAD * SEQ * HDIM];
__device__ float g_v[BATCH * NHEAD * SEQ * HDIM];
__device__ float g_ctx[BATCH * SEQ * HID];

#define BK 16

// ---------------------------------------------------------------------------
// Kernel 1: QKV projection (64x64 tile SGEMM) + fused RoPE on Q/K.
// grid = (HID/64=16, B*S/64=64, 3) ; block = 256
// Thread tile: rows ty+16i, cols tx+16j  (so d and d+32 are in the same thread)
// ---------------------------------------------------------------------------
__global__ __launch_bounds__(256) void qkv_rope_kernel(
    const float* __restrict__ X,
    const float* __restrict__ Wq, const float* __restrict__ Wk,
    const float* __restrict__ Wv,
    const int*   __restrict__ pos_ids,
    const float* __restrict__ cosb, const float* __restrict__ sinb)
{
    __shared__ float As[BK][65];   // A transposed: As[k][m]
    __shared__ float Bs[BK][65];   // Bs[k][n]

    const int tid = threadIdx.x;
    const int tx  = tid & 15, ty = tid >> 4;
    const int rowTile = blockIdx.y << 6;
    const int colTile = blockIdx.x << 6;
    const int mat = blockIdx.z;
    const float* W = (mat == 0) ? Wq : (mat == 1) ? Wk : Wv;

    const int alr = tid >> 2;          // A tile row 0..63
    const int alf = (tid & 3) << 2;    // A tile k-col (float4)
    const int blk = tid >> 4;          // B tile k-row 0..15
    const int blc = (tid & 15) << 2;   // B tile col (float4)

    float acc[4][4] = {};

    for (int k0 = 0; k0 < HID; k0 += BK) {
        float4 a4 = *(const float4*)(X + (size_t)(rowTile + alr) * HID + k0 + alf);
        As[alf + 0][alr] = a4.x; As[alf + 1][alr] = a4.y;
        As[alf + 2][alr] = a4.z; As[alf + 3][alr] = a4.w;
        float4 b4 = *(const float4*)(W + (size_t)(k0 + blk) * (NHEAD * HDIM) + colTile + blc);
        Bs[blk][blc + 0] = b4.x; Bs[blk][blc + 1] = b4.y;
        Bs[blk][blc + 2] = b4.z; Bs[blk][blc + 3] = b4.w;
        __syncthreads();
#pragma unroll
        for (int kk = 0; kk < BK; ++kk) {
            float a[4], b[4];
#pragma unroll
            for (int i = 0; i < 4; ++i) a[i] = As[kk][ty + (i << 4)];
#pragma unroll
            for (int j = 0; j < 4; ++j) b[j] = Bs[kk][tx + (j << 4)];
#pragma unroll
            for (int i = 0; i < 4; ++i)
#pragma unroll
                for (int j = 0; j < 4; ++j)
                    acc[i][j] = fmaf(a[i], b[j], acc[i][j]);
        }
        __syncthreads();
    }

    const int h = colTile >> 6;          // tile width 64 == one head
    float* dst = (mat == 0) ? g_q : (mat == 1) ? g_k : g_v;

#pragma unroll
    for (int i = 0; i < 4; ++i) {
        const int row = rowTile + ty + (i << 4);
        const int b_  = row >> 11;       // row / SEQ
        const int s_  = row & (SEQ - 1);
        const size_t base = ((size_t)(b_ * NHEAD + h) * SEQ + s_) * HDIM;
        if (mat < 2) {
            const int pos = pos_ids[b_ * SEQ + s_];
#pragma unroll
            for (int j = 0; j < 4; ++j) {
                const int d = tx + (j << 4);
                const float cs = cosb[pos * HDIM + d];
                const float sn = sinb[pos * HDIM + d];
                // rotate_half: d<32 -> -x[d+32] ; d>=32 -> x[d-32]
                const float rot = (j < 2) ? -acc[i][j + 2] : acc[i][j - 2];
                dst[base + d] = acc[i][j] * cs + rot * sn;
            }
        } else {
#pragma unroll
            for (int j = 0; j < 4; ++j)
                dst[base + tx + (j << 4)] = acc[i][j];
        }
    }
}

// ---------------------------------------------------------------------------
// Kernel 2: causal flash attention (fp32 online softmax).
// grid = (S/64=32, NH, B) ; block = 256 ; q-tiles reversed for load balance.
// Smem: Qs[64][64] + KVs[64][64] (K transposed, then V) + Ps[64][64] = 48 KB.
// Mask tile is staged through Ps (each element read+overwritten by its owner).
// ---------------------------------------------------------------------------
__global__ __launch_bounds__(256) void attn_kernel(const float* __restrict__ mask)
{
    __shared__ float Qs[64][64];    // [q][d]
    __shared__ float KVs[64][64];   // K phase: [d][kv] (transposed); V phase: [kv][d]
    __shared__ float Ps[64][64];    // mask tile, then P tile: [q][kv]

    const int tid = threadIdx.x;
    const int tx  = tid & 15, ty = tid >> 4;
    const int qi  = gridDim.x - 1 - blockIdx.x;   // big tiles first
    const int h   = blockIdx.y, b_ = blockIdx.z;
    const int q0  = qi << 6;

    const float* qbase = g_q + (size_t)(b_ * NHEAD + h) * SEQ * HDIM;
    const float* kbase = g_k + (size_t)(b_ * NHEAD + h) * SEQ * HDIM;
    const float* vbase = g_v + (size_t)(b_ * NHEAD + h) * SEQ * HDIM;
    const float* mbase = mask + (size_t)b_ * SEQ * SEQ;

    const int lr = tid >> 2;          // 0..63
    const int lc = (tid & 3) << 2;    // 0,4,8,12

    // Load Q tile [q][d] (float4, coalesced)
#pragma unroll
    for (int rep = 0; rep < 4; ++rep) {
        const int d = lc + (rep << 4);
        *(float4*)&Qs[lr][d] = *(const float4*)(qbase + (size_t)(q0 + lr) * HDIM + d);
    }

    float acc[4][4] = {};
    float mstat[4], lstat[4];
#pragma unroll
    for (int i = 0; i < 4; ++i) { mstat[i] = -1e30f; lstat[i] = 0.f; }

    for (int kt = 0; kt <= qi; ++kt) {
        const int k0 = kt << 6;
        __syncthreads();   // prev-iter Ps/KVs reads done (also covers Q load @ kt=0)

        // Load K tile TRANSPOSED into KVs[d][kv]; mask tile into Ps[q][kv]
#pragma unroll
        for (int rep = 0; rep < 4; ++rep) {
            const int d = lc + (rep << 4);
            float4 k4 = *(const float4*)(kbase + (size_t)(k0 + lr) * HDIM + d);
            KVs[d + 0][lr] = k4.x; KVs[d + 1][lr] = k4.y;
            KVs[d + 2][lr] = k4.z; KVs[d + 3][lr] = k4.w;
            *(float4*)&Ps[lr][d] = *(const float4*)(mbase + (size_t)(q0 + lr) * SEQ + k0 + d);
        }
        __syncthreads();

        // S = Q K^T
        float sc[4][4] = {};
#pragma unroll 8
        for (int dd = 0; dd < HDIM; ++dd) {
            float a[4], bb[4];
#pragma unroll
            for (int i = 0; i < 4; ++i) a[i] = Qs[ty + (i << 4)][dd];
#pragma unroll
            for (int j = 0; j < 4; ++j) bb[j] = KVs[dd][tx + (j << 4)];
#pragma unroll
            for (int i = 0; i < 4; ++i)
#pragma unroll
                for (int j = 0; j < 4; ++j)
                    sc[i][j] = fmaf(a[i], bb[j], sc[i][j]);
        }

        // scale + mask + online softmax (row group = 16 lanes sharing ty)
#pragma unroll
        for (int i = 0; i < 4; ++i) {
            const int q = ty + (i << 4);
#pragma unroll
            for (int j = 0; j < 4; ++j)
                sc[i][j] = sc[i][j] * SCALE + Ps[q][tx + (j << 4)];
            float mx = sc[i][0];
#pragma unroll
            for (int j = 1; j < 4; ++j) mx = fmaxf(mx, sc[i][j]);
#pragma unroll
            for (int off = 1; off < 16; off <<= 1)
                mx = fmaxf(mx, __shfl_xor_sync(0xffffffffu, mx, off, 16));
            const float mnew = fmaxf(mstat[i], mx);
            const float corr = __expf(mstat[i] - mnew);
            mstat[i] = mnew;
            float rs = 0.f;
#pragma unroll
            for (int j = 0; j < 4; ++j) {
                sc[i][j] = __expf(sc[i][j] - mnew);
                rs += sc[i][j];
            }
#pragma unroll
            for (int off = 1; off < 16; off <<= 1)
                rs += __shfl_xor_sync(0xffffffffu, rs, off, 16);
            lstat[i] = lstat[i] * corr + rs;
#pragma unroll
            for (int j = 0; j < 4; ++j) acc[i][j] *= corr;
            // write P (same element this thread just owned as mask)
#pragma unroll
            for (int j = 0; j < 4; ++j)
                Ps[q][tx + (j << 4)] = sc[i][j];
        }
        __syncthreads();   // P written, K reads done -> safe to overwrite KVs with V

        // Load V tile [kv][d]
#pragma unroll
        for (int rep = 0; rep < 4; ++rep) {
            const int d = lc + (rep << 4);
            *(float4*)&KVs[lr][d] = *(const float4*)(vbase + (size_t)(k0 + lr) * HDIM + d);
        }
        __syncthreads();

        // O += P V
#pragma unroll 8
        for (int kv = 0; kv < 64; ++kv) {
            float p[4], vv[4];
#pragma unroll
            for (int i = 0; i < 4; ++i) p[i] = Ps[ty + (i << 4)][kv];
#pragma unroll
            for (int j = 0; j < 4; ++j) vv[j] = KVs[kv][tx + (j << 4)];
#pragma unroll
            for (int i = 0; i < 4; ++i)
#pragma unroll
                for (int j = 0; j < 4; ++j)
                    acc[i][j] = fmaf(p[i], vv[j], acc[i][j]);
        }
    }

    // Epilogue: normalize, store into [B, S, NH*HD] context layout
    float* obase = g_ctx + (size_t)b_ * SEQ * HID + h * HDIM;
#pragma unroll
    for (int i = 0; i < 4; ++i) {
        const float inv = 1.f / lstat[i];
        const int q = q0 + ty + (i << 4);
#pragma unroll
        for (int j = 0; j < 4; ++j)
            obase[(size_t)q * HID + tx + (j << 4)] = acc[i][j] * inv;
    }
}

// ---------------------------------------------------------------------------
// Kernel 3: output projection (same SGEMM skeleton).
// grid = (16, 64) ; block = 256
// ---------------------------------------------------------------------------
__global__ __launch_bounds__(256) void out_proj_kernel(
    const float* __restrict__ Wo, float* __restrict__ out)
{
    __shared__ float As[BK][65];
    __shared__ float Bs[BK][65];

    const int tid = threadIdx.x;
    const int tx  = tid & 15, ty = tid >> 4;
    const int rowTile = blockIdx.y << 6;
    const int colTile = blockIdx.x << 6;

    const int alr = tid >> 2;
    const int alf = (tid & 3) << 2;
    const int blk = tid >> 4;
    const int blc = (tid & 15) << 2;

    float acc[4][4] = {};

    for (int k0 = 0; k0 < HID; k0 += BK) {
        float4 a4 = *(const float4*)(g_ctx + (size_t)(rowTile + alr) * HID + k0 + alf);
        As[alf + 0][alr] = a4.x; As[alf + 1][alr] = a4.y;
        As[alf + 2][alr] = a4.z; As[alf + 3][alr] = a4.w;
        float4 b4 = *(const float4*)(Wo + (size_t)(k0 + blk) * HID + colTile + blc);
        Bs[blk][blc + 0] = b4.x; Bs[blk][blc + 1] = b4.y;
        Bs[blk][blc + 2] = b4.z; Bs[blk][blc + 3] = b4.w;
        __syncthreads();
#pragma unroll
        for (int kk = 0; kk < BK; ++kk) {
            float a[4], b[4];
#pragma unroll
            for (int i = 0; i < 4; ++i) a[i] = As[kk][ty + (i << 4)];
#pragma unroll
            for (int j = 0; j < 4; ++j) b[j] = Bs[kk][tx + (j << 4)];
#pragma unroll
            for (int i = 0; i < 4; ++i)
#pragma unroll
                for (int j = 0; j < 4; ++j)
                    acc[i][j] = fmaf(a[i], b[j], acc[i][j]);
        }
        __syncthreads();
    }

#pragma unroll
    for (int i = 0; i < 4; ++i) {
        const int row = rowTile + ty + (i << 4);
#pragma unroll
        for (int j = 0; j < 4; ++j)
            out[(size_t)row * HID + colTile + tx + (j << 4)] = acc[i][j];
    }
}

// ---------------------------------------------------------------------------
extern "C" void kernel_launch(void* const* d_in, const int* in_sizes, int n_in,
                              void* d_out, int out_size)
{
    const float* X    = (const float*)d_in[0];   // hidden_states [B,S,HID]
    const float* mask = (const float*)d_in[1];   // [B,1,S,S]
    const int*   pos  = (const int*)  d_in[2];   // [B,S]
    const float* cosb = (const float*)d_in[3];   // [S,HD]
    const float* sinb = (const float*)d_in[4];   // [S,HD]
    const float* Wq   = (const float*)d_in[5];
    const float* Wk   = (const float*)d_in[6];
    const float* Wv   = (const float*)d_in[7];
    const float* Wo   = (const float*)d_in[8];
    float* out = (float*)d_out;

    dim3 g1(HID / 64, (BATCH * SEQ) / 64, 3);
    qkv_rope_kernel<<<g1, 256>>>(X, Wq, Wk, Wv, pos, cosb, sinb);

    dim3 g2(SEQ / 64, NHEAD, BATCH);
    attn_kernel<<<g2, 256>>>(mask);

    dim3 g3(HID / 64, (BATCH * SEQ) / 64);
    out_proj_kernel<<<g3, 256>>>(Wo, out);
}

// round 3
// speedup vs baseline: 1.6314x; 1.6314x over previous
#include <cuda_runtime.h>
#include <cuda_bf16.h>
#include <cstdint>

#define BATCH 2
#define SEQ   2048
#define HID   1024
#define NHEAD 16
#define HDIM  64
#define SCALE 0.125f

// ---------------- device scratch (static allocations only) ----------------
__device__ __nv_bfloat16 g_xhi[BATCH * SEQ * HID];
__device__ __nv_bfloat16 g_xlo[BATCH * SEQ * HID];
__device__ __nv_bfloat16 g_whi[4 * HID * HID];   // transposed [N][K], mats q,k,v,o
__device__ __nv_bfloat16 g_wlo[4 * HID * HID];
__device__ __nv_bfloat16 g_chi[BATCH * SEQ * HID];
__device__ __nv_bfloat16 g_clo[BATCH * SEQ * HID];
__device__ float g_q[BATCH * NHEAD * SEQ * HDIM];
__device__ float g_k[BATCH * NHEAD * SEQ * HDIM];
__device__ float g_v[BATCH * NHEAD * SEQ * HDIM];
__device__ float g_ctx[BATCH * SEQ * HID];

// ---------------- helpers ----------------
__device__ __forceinline__ uint32_t smem_u32(const void* p) {
    uint32_t a;
    asm("{ .reg .u64 t; cvta.to.shared.u64 t, %1; cvt.u32.u64 %0, t; }" : "=r"(a) : "l"(p));
    return a;
}
__device__ __forceinline__ void ldsm_x4(uint32_t* r, uint32_t addr) {
    asm volatile("ldmatrix.sync.aligned.m8n8.x4.shared.b16 {%0,%1,%2,%3}, [%4];"
                 : "=r"(r[0]), "=r"(r[1]), "=r"(r[2]), "=r"(r[3]) : "r"(addr));
}
__device__ __forceinline__ void mma_bf16(float* c, const uint32_t* a, const uint32_t* b) {
    asm volatile(
        "mma.sync.aligned.m16n8k16.row.col.f32.bf16.bf16.f32 "
        "{%0,%1,%2,%3},{%4,%5,%6,%7},{%8,%9},{%0,%1,%2,%3};"
        : "+f"(c[0]), "+f"(c[1]), "+f"(c[2]), "+f"(c[3])
        : "r"(a[0]), "r"(a[1]), "r"(a[2]), "r"(a[3]), "r"(b[0]), "r"(b[1]));
}

// ---------------- convert kernels ----------------
union BPack { __nv_bfloat16 b[8]; uint4 v; };

__global__ void split_rows_kernel(const float* __restrict__ in,
                                  __nv_bfloat16* __restrict__ hi,
                                  __nv_bfloat16* __restrict__ lo, int n8) {
    int i = blockIdx.x * blockDim.x + threadIdx.x;
    if (i >= n8) return;
    float f[8];
    *(float4*)(f)     = ((const float4*)in)[i * 2];
    *(float4*)(f + 4) = ((const float4*)in)[i * 2 + 1];
    BPack h, l;
#pragma unroll
    for (int j = 0; j < 8; ++j) {
        h.b[j] = __float2bfloat16(f[j]);
        l.b[j] = __float2bfloat16(f[j] - __bfloat162float(h.b[j]));
    }
    ((uint4*)hi)[i] = h.v;
    ((uint4*)lo)[i] = l.v;
}

__global__ void split_wT_kernel(const float* __restrict__ Wq, const float* __restrict__ Wk,
                                const float* __restrict__ Wv, const float* __restrict__ Wo) {
    __shared__ float t[32][33];
    const int mat = blockIdx.z;
    const float* W = (mat == 0) ? Wq : (mat == 1) ? Wk : (mat == 2) ? Wv : Wo;
    __nv_bfloat16* hi = g_whi + (size_t)mat * HID * HID;
    __nv_bfloat16* lo = g_wlo + (size_t)mat * HID * HID;
    const int n0 = blockIdx.x * 32, k0 = blockIdx.y * 32;
    const int tx = threadIdx.x, ty = threadIdx.y;
#pragma unroll
    for (int i = 0; i < 4; ++i)
        t[ty + 8 * i][tx] = W[(size_t)(k0 + ty + 8 * i) * HID + n0 + tx];
    __syncthreads();
#pragma unroll
    for (int i = 0; i < 4; ++i) {
        float v = t[tx][ty + 8 * i];
        __nv_bfloat16 h = __float2bfloat16(v);
        size_t idx = (size_t)(n0 + ty + 8 * i) * HID + k0 + tx;
        hi[idx] = h;
        lo[idx] = __float2bfloat16(v - __bfloat162float(h));
    }
}

// ---------------------------------------------------------------------------
// HMMA bf16 split GEMM: C[4096,1024] = A x B^T  (B stored [N][K])
// 128x128 CTA tile, BK=32, 8 warps (4 M x 2 N), warp tile 32x64.
// Smem rows padded to 80B -> conflict-free ldmatrix.
// mode 0: A = x hi/lo, B = Wq/Wk/Wv by blockIdx.z; RoPE fused for z<2;
//         scatter to g_q/g_k/g_v [B,NH,S,HD].
// mode 1: A = ctx hi/lo, B = Wo^T; store to outp.
// ---------------------------------------------------------------------------
#define PITCH 40   // bf16 elements per smem row (80 bytes)

__global__ __launch_bounds__(256) void hgemm_kernel(
    const __nv_bfloat16* __restrict__ Ahi, const __nv_bfloat16* __restrict__ Alo,
    int mode, const int* __restrict__ pos_ids,
    const float* __restrict__ cosb, const float* __restrict__ sinb,
    float* __restrict__ outp)
{
    __shared__ __nv_bfloat16 sAh[128 * PITCH], sAl[128 * PITCH];
    __shared__ __nv_bfloat16 sBh[128 * PITCH], sBl[128 * PITCH];

    const int tid = threadIdx.x;
    const int lane = tid & 31, wid = tid >> 5;
    const int wm = wid & 3, wn = wid >> 2;
    const int z = blockIdx.z;
    const int row0 = blockIdx.y << 7, col0 = blockIdx.x << 7;
    const int wsel = (mode == 0) ? z : 3;
    const __nv_bfloat16* Bhi = g_whi + (size_t)wsel * HID * HID;
    const __nv_bfloat16* Blo = g_wlo + (size_t)wsel * HID * HID;

    const uint32_t uAh = smem_u32(sAh), uAl = smem_u32(sAl);
    const uint32_t uBh = smem_u32(sBh), uBl = smem_u32(sBl);

    float acc[2][8][4];
#pragma unroll
    for (int t = 0; t < 2; ++t)
#pragma unroll
        for (int j = 0; j < 8; ++j)
#pragma unroll
            for (int e = 0; e < 4; ++e) acc[t][j][e] = 0.f;

    // loader coords: 2 threads per row, each 2 consecutive 16B chunks (32B)
    const int lrow = tid >> 1;
    const int lch  = (tid & 1) * 2;                 // chunk 0 or 2
    const uint32_t s_off = lrow * 80 + lch * 16;    // smem byte offset

    // ldmatrix per-lane byte offsets (chunk granularity = 16B = 8 bf16)
    const int a_row = wm * 32 + (lane & 15);
    const int a_ch  = lane >> 4;                    // 0/1 -> k chunk
    const int b_row = wn * 64 + (lane & 7) + ((lane & 16) >> 1);
    const int b_ch  = (lane >> 3) & 1;

    for (int it = 0; it < HID / 32; ++it) {
        const int k0 = it * 32;
        // ---- stage 4 tiles ----
        {
            const size_t ga = (size_t)(row0 + lrow) * HID + k0 + lch * 8;
            const size_t gb = (size_t)(col0 + lrow) * HID + k0 + lch * 8;
            uint4 vah0 = *(const uint4*)(Ahi + ga);
            uint4 vah1 = *(const uint4*)(Ahi + ga + 8);
            uint4 val0 = *(const uint4*)(Alo + ga);
            uint4 val1 = *(const uint4*)(Alo + ga + 8);
            uint4 vbh0 = *(const uint4*)(Bhi + gb);
            uint4 vbh1 = *(const uint4*)(Bhi + gb + 8);
            uint4 vbl0 = *(const uint4*)(Blo + gb);
            uint4 vbl1 = *(const uint4*)(Blo + gb + 8);
            *(uint4*)((char*)sAh + s_off)      = vah0;
            *(uint4*)((char*)sAh + s_off + 16) = vah1;
            *(uint4*)((char*)sAl + s_off)      = val0;
            *(uint4*)((char*)sAl + s_off + 16) = val1;
            *(uint4*)((char*)sBh + s_off)      = vbh0;
            *(uint4*)((char*)sBh + s_off + 16) = vbh1;
            *(uint4*)((char*)sBl + s_off)      = vbl0;
            *(uint4*)((char*)sBl + s_off + 16) = vbl1;
        }
        __syncthreads();

        // ---- compute: 2 k16 halves x 3 products ----
#pragma unroll
        for (int kh = 0; kh < 2; ++kh) {
            uint32_t aH[2][4], aL[2][4], bH[4][4], bL[4][4];
            const uint32_t a_off = a_row * 80 + (kh * 2 + a_ch) * 16;
            const uint32_t b_off = b_row * 80 + (kh * 2 + b_ch) * 16;
            ldsm_x4(aH[0], uAh + a_off);
            ldsm_x4(aH[1], uAh + a_off + 16 * 80);
            ldsm_x4(aL[0], uAl + a_off);
            ldsm_x4(aL[1], uAl + a_off + 16 * 80);
#pragma unroll
            for (int g = 0; g < 4; ++g) {
                ldsm_x4(bH[g], uBh + b_off + g * (16 * 80));
                ldsm_x4(bL[g], uBl + b_off + g * (16 * 80));
            }
#pragma unroll
            for (int t = 0; t < 2; ++t)
#pragma unroll
                for (int g = 0; g < 4; ++g) {
                    mma_bf16(acc[t][2 * g],     aH[t], &bH[g][0]);
                    mma_bf16(acc[t][2 * g + 1], aH[t], &bH[g][2]);
                    mma_bf16(acc[t][2 * g],     aH[t], &bL[g][0]);
                    mma_bf16(acc[t][2 * g + 1], aH[t], &bL[g][2]);
                    mma_bf16(acc[t][2 * g],     aL[t], &bH[g][0]);
                    mma_bf16(acc[t][2 * g + 1], aL[t], &bH[g][2]);
                }
        }
        __syncthreads();
    }

    // ---------------- epilogue ----------------
    const int q2 = (lane & 3) * 2;
#pragma unroll
    for (int t = 0; t < 2; ++t) {
#pragma unroll
        for (int h2 = 0; h2 < 2; ++h2) {
            const int row = row0 + wm * 32 + t * 16 + (lane >> 2) + h2 * 8;
            if (mode == 1) {
                float* dst = outp + (size_t)row * HID + col0 + wn * 64 + q2;
#pragma unroll
                for (int j = 0; j < 8; ++j)
                    *(float2*)(dst + j * 8) =
                        make_float2(acc[t][j][h2 * 2], acc[t][j][h2 * 2 + 1]);
            } else {
                const int b_ = row >> 11, s_ = row & (SEQ - 1);
                const int h = (col0 >> 6) + wn;
                if (z == 2) {
                    float* dst = g_v + ((size_t)(b_ * NHEAD + h) * SEQ + s_) * HDIM + q2;
#pragma unroll
                    for (int j = 0; j < 8; ++j)
                        *(float2*)(dst + j * 8) =
                            make_float2(acc[t][j][h2 * 2], acc[t][j][h2 * 2 + 1]);
                } else {
                    const int pos = pos_ids[b_ * SEQ + s_];
                    const float* cr = cosb + pos * HDIM;
                    const float* sr = sinb + pos * HDIM;
                    float* dst = ((z == 0) ? g_q : g_k)
                               + ((size_t)(b_ * NHEAD + h) * SEQ + s_) * HDIM + q2;
#pragma unroll
                    for (int j = 0; j < 4; ++j) {
                        float o1[2], o2[2];
#pragma unroll
                        for (int e = 0; e < 2; ++e) {
                            const int d = j * 8 + q2 + e;
                            const float x = acc[t][j][h2 * 2 + e];
                            const float y = acc[t][j + 4][h2 * 2 + e];
                            o1[e] = x * cr[d] - y * sr[d];
                            o2[e] = y * cr[d + 32] + x * sr[d + 32];
                        }
                        *(float2*)(dst + j * 8)      = make_float2(o1[0], o1[1]);
                        *(float2*)(dst + j * 8 + 32) = make_float2(o2[0], o2[1]);
                    }
                }
            }
        }
    }
}

// ---------------------------------------------------------------------------
// Flash attention (SIMT fp32 — HMMA conversion is next round's target)
// ---------------------------------------------------------------------------
__global__ __launch_bounds__(256) void attn_kernel(const float* __restrict__ mask)
{
    __shared__ float Qs[64][64];
    __shared__ float KVs[64][64];
    __shared__ float Ps[64][64];

    const int tid = threadIdx.x;
    const int tx  = tid & 15, ty = tid >> 4;
    const int qi  = gridDim.x - 1 - blockIdx.x;
    const int h   = blockIdx.y, b_ = blockIdx.z;
    const int q0  = qi << 6;

    const float* qbase = g_q + (size_t)(b_ * NHEAD + h) * SEQ * HDIM;
    const float* kbase = g_k + (size_t)(b_ * NHEAD + h) * SEQ * HDIM;
    const float* vbase = g_v + (size_t)(b_ * NHEAD + h) * SEQ * HDIM;
    const float* mbase = mask + (size_t)b_ * SEQ * SEQ;

    const int lr = tid >> 2;
    const int lc = (tid & 3) << 2;

#pragma unroll
    for (int rep = 0; rep < 4; ++rep) {
        const int d = lc + (rep << 4);
        *(float4*)&Qs[lr][d] = *(const float4*)(qbase + (size_t)(q0 + lr) * HDIM + d);
    }

    float acc[4][4] = {};
    float mstat[4], lstat[4];
#pragma unroll
    for (int i = 0; i < 4; ++i) { mstat[i] = -1e30f; lstat[i] = 0.f; }

    for (int kt = 0; kt <= qi; ++kt) {
        const int k0 = kt << 6;
        __syncthreads();
#pragma unroll
        for (int rep = 0; rep < 4; ++rep) {
            const int d = lc + (rep << 4);
            float4 k4 = *(const float4*)(kbase + (size_t)(k0 + lr) * HDIM + d);
            KVs[d + 0][lr] = k4.x; KVs[d + 1][lr] = k4.y;
            KVs[d + 2][lr] = k4.z; KVs[d + 3][lr] = k4.w;
            *(float4*)&Ps[lr][d] = *(const float4*)(mbase + (size_t)(q0 + lr) * SEQ + k0 + d);
        }
        __syncthreads();

        float sc[4][4] = {};
#pragma unroll 8
        for (int dd = 0; dd < HDIM; ++dd) {
            float a[4], bb[4];
#pragma unroll
            for (int i = 0; i < 4; ++i) a[i] = Qs[ty + (i << 4)][dd];
#pragma unroll
            for (int j = 0; j < 4; ++j) bb[j] = KVs[dd][tx + (j << 4)];
#pragma unroll
            for (int i = 0; i < 4; ++i)
#pragma unroll
                for (int j = 0; j < 4; ++j)
                    sc[i][j] = fmaf(a[i], bb[j], sc[i][j]);
        }

#pragma unroll
        for (int i = 0; i < 4; ++i) {
            const int q = ty + (i << 4);
#pragma unroll
            for (int j = 0; j < 4; ++j)
                sc[i][j] = sc[i][j] * SCALE + Ps[q][tx + (j << 4)];
            float mx = sc[i][0];
#pragma unroll
            for (int j = 1; j < 4; ++j) mx = fmaxf(mx, sc[i][j]);
#pragma unroll
            for (int off = 1; off < 16; off <<= 1)
                mx = fmaxf(mx, __shfl_xor_sync(0xffffffffu, mx, off, 16));
            const float mnew = fmaxf(mstat[i], mx);
            const float corr = __expf(mstat[i] - mnew);
            mstat[i] = mnew;
            float rs = 0.f;
#pragma unroll
            for (int j = 0; j < 4; ++j) {
                sc[i][j] = __expf(sc[i][j] - mnew);
                rs += sc[i][j];
            }
#pragma unroll
            for (int off = 1; off < 16; off <<= 1)
                rs += __shfl_xor_sync(0xffffffffu, rs, off, 16);
            lstat[i] = lstat[i] * corr + rs;
#pragma unroll
            for (int j = 0; j < 4; ++j) acc[i][j] *= corr;
#pragma unroll
            for (int j = 0; j < 4; ++j)
                Ps[q][tx + (j << 4)] = sc[i][j];
        }
        __syncthreads();

#pragma unroll
        for (int rep = 0; rep < 4; ++rep) {
            const int d = lc + (rep << 4);
            *(float4*)&KVs[lr][d] = *(const float4*)(vbase + (size_t)(k0 + lr) * HDIM + d);
        }
        __syncthreads();

#pragma unroll 8
        for (int kv = 0; kv < 64; ++kv) {
            float p[4], vv[4];
#pragma unroll
            for (int i = 0; i < 4; ++i) p[i] = Ps[ty + (i << 4)][kv];
#pragma unroll
            for (int j = 0; j < 4; ++j) vv[j] = KVs[kv][tx + (j << 4)];
#pragma unroll
            for (int i = 0; i < 4; ++i)
#pragma unroll
                for (int j = 0; j < 4; ++j)
                    acc[i][j] = fmaf(p[i], vv[j], acc[i][j]);
        }
    }

    float* obase = g_ctx + (size_t)b_ * SEQ * HID + h * HDIM;
#pragma unroll
    for (int i = 0; i < 4; ++i) {
        const float inv = 1.f / lstat[i];
        const int q = q0 + ty + (i << 4);
#pragma unroll
        for (int j = 0; j < 4; ++j)
            obase[(size_t)q * HID + tx + (j << 4)] = acc[i][j] * inv;
    }
}

// ---------------------------------------------------------------------------
extern "C" void kernel_launch(void* const* d_in, const int* in_sizes, int n_in,
                              void* d_out, int out_size)
{
    const float* X    = (const float*)d_in[0];
    const float* mask = (const float*)d_in[1];
    const int*   pos  = (const int*)  d_in[2];
    const float* cosb = (const float*)d_in[3];
    const float* sinb = (const float*)d_in[4];
    const float* Wq   = (const float*)d_in[5];
    const float* Wk   = (const float*)d_in[6];
    const float* Wv   = (const float*)d_in[7];
    const float* Wo   = (const float*)d_in[8];
    float* out = (float*)d_out;

    __nv_bfloat16 *xhi, *xlo, *chi, *clo;
    cudaGetSymbolAddress((void**)&xhi, g_xhi);
    cudaGetSymbolAddress((void**)&xlo, g_xlo);
    cudaGetSymbolAddress((void**)&chi, g_chi);
    cudaGetSymbolAddress((void**)&clo, g_clo);
    float* ctx;
    cudaGetSymbolAddress((void**)&ctx, g_ctx);

    // 1) convert inputs to bf16 hi/lo
    {
        int n8 = BATCH * SEQ * HID / 8;
        split_rows_kernel<<<(n8 + 255) / 256, 256>>>(X, xhi, xlo, n8);
        dim3 gw(HID / 32, HID / 32, 4);
        split_wT_kernel<<<gw, dim3(32, 8)>>>(Wq, Wk, Wv, Wo);
    }
    // 2) QKV projection + RoPE (HMMA)
    {
        dim3 g(HID / 128, (BATCH * SEQ) / 128, 3);
        hgemm_kernel<<<g, 256>>>(xhi, xlo, 0, pos, cosb, sinb, nullptr);
    }
    // 3) attention
    {
        dim3 g(SEQ / 64, NHEAD, BATCH);
        attn_kernel<<<g, 256>>>(mask);
    }
    // 4) convert ctx, 5) output projection (HMMA)
    {
        int n8 = BATCH * SEQ * HID / 8;
        split_rows_kernel<<<(n8 + 255) / 256, 256>>>(ctx, chi, clo, n8);
        dim3 g(HID / 128, (BATCH * SEQ) / 128, 1);
        hgemm_kernel<<<g, 256>>>(chi, clo, 1, pos, cosb, sinb, out);
    }
}

// round 4
// speedup vs baseline: 2.9052x; 1.7808x over previous
#include <cuda_runtime.h>
#include <cuda_bf16.h>
#include <cstdint>

#define BATCH 2
#define SEQ   2048
#define HID   1024
#define NHEAD 16
#define HDIM  64
#define SCALE 0.125f

// ---------------- device scratch (static allocations only) ----------------
__device__ __nv_bfloat16 g_xhi[BATCH * SEQ * HID];
__device__ __nv_bfloat16 g_xlo[BATCH * SEQ * HID];
__device__ __nv_bfloat16 g_whi[4 * HID * HID];   // transposed [N][K], mats q,k,v,o
__device__ __nv_bfloat16 g_wlo[4 * HID * HID];
__device__ __nv_bfloat16 g_chi[BATCH * SEQ * HID];
__device__ __nv_bfloat16 g_clo[BATCH * SEQ * HID];
__device__ __nv_bfloat16 g_qhi[BATCH * NHEAD * SEQ * HDIM];
__device__ __nv_bfloat16 g_qlo[BATCH * NHEAD * SEQ * HDIM];
__device__ __nv_bfloat16 g_khi[BATCH * NHEAD * SEQ * HDIM];
__device__ __nv_bfloat16 g_klo[BATCH * NHEAD * SEQ * HDIM];
__device__ __nv_bfloat16 g_vhi[BATCH * NHEAD * SEQ * HDIM];
__device__ __nv_bfloat16 g_vlo[BATCH * NHEAD * SEQ * HDIM];

// ---------------- helpers ----------------
__device__ __forceinline__ uint32_t smem_u32(const void* p) {
    uint32_t a;
    asm("{ .reg .u64 t; cvta.to.shared.u64 t, %1; cvt.u32.u64 %0, t; }" : "=r"(a) : "l"(p));
    return a;
}
__device__ __forceinline__ void ldsm_x4(uint32_t* r, uint32_t addr) {
    asm volatile("ldmatrix.sync.aligned.m8n8.x4.shared.b16 {%0,%1,%2,%3}, [%4];"
                 : "=r"(r[0]), "=r"(r[1]), "=r"(r[2]), "=r"(r[3]) : "r"(addr));
}
__device__ __forceinline__ void ldsm_x4_t(uint32_t* r, uint32_t addr) {
    asm volatile("ldmatrix.sync.aligned.m8n8.x4.trans.shared.b16 {%0,%1,%2,%3}, [%4];"
                 : "=r"(r[0]), "=r"(r[1]), "=r"(r[2]), "=r"(r[3]) : "r"(addr));
}
__device__ __forceinline__ void mma_bf16(float* c, const uint32_t* a, const uint32_t* b) {
    asm volatile(
        "mma.sync.aligned.m16n8k16.row.col.f32.bf16.bf16.f32 "
        "{%0,%1,%2,%3},{%4,%5,%6,%7},{%8,%9},{%0,%1,%2,%3};"
        : "+f"(c[0]), "+f"(c[1]), "+f"(c[2]), "+f"(c[3])
        : "r"(a[0]), "r"(a[1]), "r"(a[2]), "r"(a[3]), "r"(b[0]), "r"(b[1]));
}
// split (a,b) into packed bf16x2 hi and lo parts
__device__ __forceinline__ void split2(float a, float b, uint32_t& hi, uint32_t& lo) {
    __nv_bfloat162 h = __floats2bfloat162_rn(a, b);
    float2 hf = __bfloat1622float2(h);
    __nv_bfloat162 l = __floats2bfloat162_rn(a - hf.x, b - hf.y);
    hi = *(uint32_t*)&h;
    lo = *(uint32_t*)&l;
}

// ---------------- convert kernels ----------------
union BPack { __nv_bfloat16 b[8]; uint4 v; };

__global__ void split_rows_kernel(const float* __restrict__ in,
                                  __nv_bfloat16* __restrict__ hi,
                                  __nv_bfloat16* __restrict__ lo, int n8) {
    int i = blockIdx.x * blockDim.x + threadIdx.x;
    if (i >= n8) return;
    float f[8];
    *(float4*)(f)     = ((const float4*)in)[i * 2];
    *(float4*)(f + 4) = ((const float4*)in)[i * 2 + 1];
    BPack h, l;
#pragma unroll
    for (int j = 0; j < 8; ++j) {
        h.b[j] = __float2bfloat16(f[j]);
        l.b[j] = __float2bfloat16(f[j] - __bfloat162float(h.b[j]));
    }
    ((uint4*)hi)[i] = h.v;
    ((uint4*)lo)[i] = l.v;
}

__global__ void split_wT_kernel(const float* __restrict__ Wq, const float* __restrict__ Wk,
                                const float* __restrict__ Wv, const float* __restrict__ Wo) {
    __shared__ float t[32][33];
    const int mat = blockIdx.z;
    const float* W = (mat == 0) ? Wq : (mat == 1) ? Wk : (mat == 2) ? Wv : Wo;
    __nv_bfloat16* hi = g_whi + (size_t)mat * HID * HID;
    __nv_bfloat16* lo = g_wlo + (size_t)mat * HID * HID;
    const int n0 = blockIdx.x * 32, k0 = blockIdx.y * 32;
    const int tx = threadIdx.x, ty = threadIdx.y;
#pragma unroll
    for (int i = 0; i < 4; ++i)
        t[ty + 8 * i][tx] = W[(size_t)(k0 + ty + 8 * i) * HID + n0 + tx];
    __syncthreads();
#pragma unroll
    for (int i = 0; i < 4; ++i) {
        float v = t[tx][ty + 8 * i];
        __nv_bfloat16 h = __float2bfloat16(v);
        size_t idx = (size_t)(n0 + ty + 8 * i) * HID + k0 + tx;
        hi[idx] = h;
        lo[idx] = __float2bfloat16(v - __bfloat162float(h));
    }
}

// ---------------------------------------------------------------------------
// HMMA bf16 split GEMM (as R2) — mode 0: QKV + RoPE -> bf16 hi/lo outputs,
// Q pre-scaled by SCALE. mode 1: out-projection -> fp32 out.
// ---------------------------------------------------------------------------
#define PITCH 40   // bf16 elements per smem row (80 bytes)

__global__ __launch_bounds__(256) void hgemm_kernel(
    const __nv_bfloat16* __restrict__ Ahi, const __nv_bfloat16* __restrict__ Alo,
    int mode, const int* __restrict__ pos_ids,
    const float* __restrict__ cosb, const float* __restrict__ sinb,
    float* __restrict__ outp)
{
    __shared__ __nv_bfloat16 sAh[128 * PITCH], sAl[128 * PITCH];
    __shared__ __nv_bfloat16 sBh[128 * PITCH], sBl[128 * PITCH];

    const int tid = threadIdx.x;
    const int lane = tid & 31, wid = tid >> 5;
    const int wm = wid & 3, wn = wid >> 2;
    const int z = blockIdx.z;
    const int row0 = blockIdx.y << 7, col0 = blockIdx.x << 7;
    const int wsel = (mode == 0) ? z : 3;
    const __nv_bfloat16* Bhi = g_whi + (size_t)wsel * HID * HID;
    const __nv_bfloat16* Blo = g_wlo + (size_t)wsel * HID * HID;

    const uint32_t uAh = smem_u32(sAh), uAl = smem_u32(sAl);
    const uint32_t uBh = smem_u32(sBh), uBl = smem_u32(sBl);

    float acc[2][8][4];
#pragma unroll
    for (int t = 0; t < 2; ++t)
#pragma unroll
        for (int j = 0; j < 8; ++j)
#pragma unroll
            for (int e = 0; e < 4; ++e) acc[t][j][e] = 0.f;

    const int lrow = tid >> 1;
    const int lch  = (tid & 1) * 2;
    const uint32_t s_off = lrow * 80 + lch * 16;

    const int a_row = wm * 32 + (lane & 15);
    const int a_ch  = lane >> 4;
    const int b_row = wn * 64 + (lane & 7) + ((lane & 16) >> 1);
    const int b_ch  = (lane >> 3) & 1;

    for (int it = 0; it < HID / 32; ++it) {
        const int k0 = it * 32;
        {
            const size_t ga = (size_t)(row0 + lrow) * HID + k0 + lch * 8;
            const size_t gb = (size_t)(col0 + lrow) * HID + k0 + lch * 8;
            uint4 vah0 = *(const uint4*)(Ahi + ga);
            uint4 vah1 = *(const uint4*)(Ahi + ga + 8);
            uint4 val0 = *(const uint4*)(Alo + ga);
            uint4 val1 = *(const uint4*)(Alo + ga + 8);
            uint4 vbh0 = *(const uint4*)(Bhi + gb);
            uint4 vbh1 = *(const uint4*)(Bhi + gb + 8);
            uint4 vbl0 = *(const uint4*)(Blo + gb);
            uint4 vbl1 = *(const uint4*)(Blo + gb + 8);
            *(uint4*)((char*)sAh + s_off)      = vah0;
            *(uint4*)((char*)sAh + s_off + 16) = vah1;
            *(uint4*)((char*)sAl + s_off)      = val0;
            *(uint4*)((char*)sAl + s_off + 16) = val1;
            *(uint4*)((char*)sBh + s_off)      = vbh0;
            *(uint4*)((char*)sBh + s_off + 16) = vbh1;
            *(uint4*)((char*)sBl + s_off)      = vbl0;
            *(uint4*)((char*)sBl + s_off + 16) = vbl1;
        }
        __syncthreads();
#pragma unroll
        for (int kh = 0; kh < 2; ++kh) {
            uint32_t aH[2][4], aL[2][4], bH[4][4], bL[4][4];
            const uint32_t a_off = a_row * 80 + (kh * 2 + a_ch) * 16;
            const uint32_t b_off = b_row * 80 + (kh * 2 + b_ch) * 16;
            ldsm_x4(aH[0], uAh + a_off);
            ldsm_x4(aH[1], uAh + a_off + 16 * 80);
            ldsm_x4(aL[0], uAl + a_off);
            ldsm_x4(aL[1], uAl + a_off + 16 * 80);
#pragma unroll
            for (int g = 0; g < 4; ++g) {
                ldsm_x4(bH[g], uBh + b_off + g * (16 * 80));
                ldsm_x4(bL[g], uBl + b_off + g * (16 * 80));
            }
#pragma unroll
            for (int t = 0; t < 2; ++t)
#pragma unroll
                for (int g = 0; g < 4; ++g) {
                    mma_bf16(acc[t][2 * g],     aH[t], &bH[g][0]);
                    mma_bf16(acc[t][2 * g + 1], aH[t], &bH[g][2]);
                    mma_bf16(acc[t][2 * g],     aH[t], &bL[g][0]);
                    mma_bf16(acc[t][2 * g + 1], aH[t], &bL[g][2]);
                    mma_bf16(acc[t][2 * g],     aL[t], &bH[g][0]);
                    mma_bf16(acc[t][2 * g + 1], aL[t], &bH[g][2]);
                }
        }
        __syncthreads();
    }

    // ---------------- epilogue ----------------
    const int q2 = (lane & 3) * 2;
#pragma unroll
    for (int t = 0; t < 2; ++t) {
#pragma unroll
        for (int h2 = 0; h2 < 2; ++h2) {
            const int row = row0 + wm * 32 + t * 16 + (lane >> 2) + h2 * 8;
            if (mode == 1) {
                float* dst = outp + (size_t)row * HID + col0 + wn * 64 + q2;
#pragma unroll
                for (int j = 0; j < 8; ++j)
                    *(float2*)(dst + j * 8) =
                        make_float2(acc[t][j][h2 * 2], acc[t][j][h2 * 2 + 1]);
            } else {
                const int b_ = row >> 11, s_ = row & (SEQ - 1);
                const int h = (col0 >> 6) + wn;
                const size_t base = ((size_t)(b_ * NHEAD + h) * SEQ + s_) * HDIM;
                if (z == 2) {
#pragma unroll
                    for (int j = 0; j < 8; ++j) {
                        uint32_t hi, lo;
                        split2(acc[t][j][h2 * 2], acc[t][j][h2 * 2 + 1], hi, lo);
                        *(uint32_t*)(g_vhi + base + j * 8 + q2) = hi;
                        *(uint32_t*)(g_vlo + base + j * 8 + q2) = lo;
                    }
                } else {
                    const int pos = pos_ids[b_ * SEQ + s_];
                    const float* cr = cosb + pos * HDIM;
                    const float* sr = sinb + pos * HDIM;
                    __nv_bfloat16* dhi = (z == 0) ? g_qhi : g_khi;
                    __nv_bfloat16* dlo = (z == 0) ? g_qlo : g_klo;
                    const float sc_ = (z == 0) ? SCALE : 1.0f;
#pragma unroll
                    for (int j = 0; j < 4; ++j) {
                        float o1[2], o2[2];
#pragma unroll
                        for (int e = 0; e < 2; ++e) {
                            const int d = j * 8 + q2 + e;
                            const float x = acc[t][j][h2 * 2 + e];
                            const float y = acc[t][j + 4][h2 * 2 + e];
                            o1[e] = (x * cr[d] - y * sr[d]) * sc_;
                            o2[e] = (y * cr[d + 32] + x * sr[d + 32]) * sc_;
                        }
                        uint32_t hi, lo;
                        split2(o1[0], o1[1], hi, lo);
                        *(uint32_t*)(dhi + base + j * 8 + q2) = hi;
                        *(uint32_t*)(dlo + base + j * 8 + q2) = lo;
                        split2(o2[0], o2[1], hi, lo);
                        *(uint32_t*)(dhi + base + j * 8 + q2 + 32) = hi;
                        *(uint32_t*)(dlo + base + j * 8 + q2 + 32) = lo;
                    }
                }
            }
        }
    }
}

// ---------------------------------------------------------------------------
// HMMA flash attention: 128 q-rows x 64 kv per tile, 8 warps x 16 q-rows.
// Causal mask computed analytically. P hi/lo split + V hi/lo: 3 products.
// Writes ctx directly as bf16 hi/lo.
// ---------------------------------------------------------------------------
#define AP 144   // bytes per smem row (64 bf16 = 128B + 16B pad)

__global__ __launch_bounds__(256) void attn_kernel()
{
    __shared__ __nv_bfloat16 sKh[64 * 72], sKl[64 * 72];
    __shared__ __nv_bfloat16 sVh[64 * 72], sVl[64 * 72];

    const int tid = threadIdx.x, lane = tid & 31, wid = tid >> 5;
    const int qi = gridDim.x - 1 - blockIdx.x;   // big tiles first
    const int h = blockIdx.y, b_ = blockIdx.z;
    const int q0 = qi << 7;
    const size_t hb = (size_t)(b_ * NHEAD + h) * SEQ * HDIM;
    const __nv_bfloat16 *qhi = g_qhi + hb, *qlo = g_qlo + hb;
    const __nv_bfloat16 *khi = g_khi + hb, *klo = g_klo + hb;
    const __nv_bfloat16 *vhi = g_vhi + hb, *vlo = g_vlo + hb;

    const uint32_t uKh = smem_u32(sKh), uKl = smem_u32(sKl);
    const uint32_t uVh = smem_u32(sVh), uVl = smem_u32(sVl);

    // ---- stage Q (rows 0-63 -> K bufs, 64-127 -> V bufs) ----
    {
        const int r = tid >> 1, half = tid & 1;
        const __nv_bfloat16* sh = qhi + (size_t)(q0 + r) * HDIM + half * 32;
        const __nv_bfloat16* sl = qlo + (size_t)(q0 + r) * HDIM + half * 32;
        char* dh = (char*)(r < 64 ? sKh : sVh) + (r & 63) * AP + half * 64;
        char* dl = (char*)(r < 64 ? sKl : sVl) + (r & 63) * AP + half * 64;
#pragma unroll
        for (int c = 0; c < 4; ++c) {
            *(uint4*)(dh + c * 16) = *(const uint4*)(sh + c * 8);
            *(uint4*)(dl + c * 16) = *(const uint4*)(sl + c * 8);
        }
    }
    __syncthreads();

    // ---- Q fragments (A-layout), 4 k16-chunks, hi/lo ----
    uint32_t qfh[4][4], qfl[4][4];
    {
        const uint32_t bh = (wid < 4) ? uKh : uVh;
        const uint32_t bl = (wid < 4) ? uKl : uVl;
        const int arow = (wid & 3) * 16 + (lane & 15);
        const int ach = lane >> 4;
#pragma unroll
        for (int kc = 0; kc < 4; ++kc) {
            const uint32_t off = arow * AP + (kc * 2 + ach) * 16;
            ldsm_x4(qfh[kc], bh + off);
            ldsm_x4(qfl[kc], bl + off);
        }
    }

    float oacc[8][4];
#pragma unroll
    for (int g = 0; g < 8; ++g)
#pragma unroll
        for (int e = 0; e < 4; ++e) oacc[g][e] = 0.f;
    float m0 = -1e30f, m1 = -1e30f, l0 = 0.f, l1 = 0.f;

    const int wbase = q0 + wid * 16;
    const int nt = (q0 >> 6) + 2;
    const int lrow = tid >> 2, lq = tid & 3;
    const int brow_ = (lane & 7) + ((lane & 16) >> 1);
    const int bch_ = (lane >> 3) & 1;
    const int vrow_ = lane & 15;
    const int vcol_ = (lane & 16) ? 8 : 0;

    for (int kt = 0; kt < nt; ++kt) {
        const int k0 = kt << 6;
        __syncthreads();
        {   // load K/V tiles hi/lo
            const size_t src = (size_t)(k0 + lrow) * HDIM + lq * 16;
            const uint32_t doff = lrow * AP + lq * 32;
            uint4 a0 = *(const uint4*)(khi + src), a1 = *(const uint4*)(khi + src + 8);
            uint4 b0 = *(const uint4*)(klo + src), b1 = *(const uint4*)(klo + src + 8);
            uint4 c0 = *(const uint4*)(vhi + src), c1 = *(const uint4*)(vhi + src + 8);
            uint4 d0 = *(const uint4*)(vlo + src), d1 = *(const uint4*)(vlo + src + 8);
            *(uint4*)((char*)sKh + doff) = a0; *(uint4*)((char*)sKh + doff + 16) = a1;
            *(uint4*)((char*)sKl + doff) = b0; *(uint4*)((char*)sKl + doff + 16) = b1;
            *(uint4*)((char*)sVh + doff) = c0; *(uint4*)((char*)sVh + doff + 16) = c1;
            *(uint4*)((char*)sVl + doff) = d0; *(uint4*)((char*)sVl + doff + 16) = d1;
        }
        __syncthreads();
        if (k0 > wbase + 15) continue;   // warp fully masked

        // ---- S = Q K^T ----
        float sc[8][4];
#pragma unroll
        for (int g = 0; g < 8; ++g)
#pragma unroll
            for (int e = 0; e < 4; ++e) sc[g][e] = 0.f;
#pragma unroll
        for (int kc = 0; kc < 4; ++kc) {
#pragma unroll
            for (int g = 0; g < 4; ++g) {
                uint32_t bH[4], bL[4];
                const uint32_t boff = (g * 16 + brow_) * AP + (kc * 2 + bch_) * 16;
                ldsm_x4(bH, uKh + boff);
                ldsm_x4(bL, uKl + boff);
                mma_bf16(sc[2 * g],     qfh[kc], &bH[0]);
                mma_bf16(sc[2 * g + 1], qfh[kc], &bH[2]);
                mma_bf16(sc[2 * g],     qfh[kc], &bL[0]);
                mma_bf16(sc[2 * g + 1], qfh[kc], &bL[2]);
                mma_bf16(sc[2 * g],     qfl[kc], &bH[0]);
                mma_bf16(sc[2 * g + 1], qfl[kc], &bH[2]);
            }
        }

        // ---- causal mask (analytic) ----
        const int r0 = wbase + (lane >> 2), r1 = r0 + 8;
        if (k0 + 63 > wbase) {
#pragma unroll
            for (int g = 0; g < 8; ++g) {
#pragma unroll
                for (int e = 0; e < 2; ++e) {
                    const int col = k0 + 8 * g + 2 * (lane & 3) + e;
                    if (col > r0) sc[g][e] = -1e9f;
                    if (col > r1) sc[g][2 + e] = -1e9f;
                }
            }
        }

        // ---- online softmax ----
        float mx0 = sc[0][0], mx1 = sc[0][2];
#pragma unroll
        for (int g = 0; g < 8; ++g) {
            mx0 = fmaxf(mx0, fmaxf(sc[g][0], sc[g][1]));
            mx1 = fmaxf(mx1, fmaxf(sc[g][2], sc[g][3]));
        }
        mx0 = fmaxf(mx0, __shfl_xor_sync(0xffffffffu, mx0, 1));
        mx0 = fmaxf(mx0, __shfl_xor_sync(0xffffffffu, mx0, 2));
        mx1 = fmaxf(mx1, __shfl_xor_sync(0xffffffffu, mx1, 1));
        mx1 = fmaxf(mx1, __shfl_xor_sync(0xffffffffu, mx1, 2));
        const float nm0 = fmaxf(m0, mx0), nm1 = fmaxf(m1, mx1);
        const float cr0 = __expf(m0 - nm0), cr1 = __expf(m1 - nm1);
        m0 = nm0; m1 = nm1;
        float rs0 = 0.f, rs1 = 0.f;
#pragma unroll
        for (int g = 0; g < 8; ++g) {
            sc[g][0] = __expf(sc[g][0] - nm0);
            sc[g][1] = __expf(sc[g][1] - nm0);
            sc[g][2] = __expf(sc[g][2] - nm1);
            sc[g][3] = __expf(sc[g][3] - nm1);
            rs0 += sc[g][0] + sc[g][1];
            rs1 += sc[g][2] + sc[g][3];
        }
        rs0 += __shfl_xor_sync(0xffffffffu, rs0, 1);
        rs0 += __shfl_xor_sync(0xffffffffu, rs0, 2);
        rs1 += __shfl_xor_sync(0xffffffffu, rs1, 1);
        rs1 += __shfl_xor_sync(0xffffffffu, rs1, 2);
        l0 = l0 * cr0 + rs0;
        l1 = l1 * cr1 + rs1;
#pragma unroll
        for (int g = 0; g < 8; ++g) {
            oacc[g][0] *= cr0; oacc[g][1] *= cr0;
            oacc[g][2] *= cr1; oacc[g][3] *= cr1;
        }

        // ---- pack P into A-fragments (hi/lo) ----
        uint32_t pah[4][4], pal[4][4];
#pragma unroll
        for (int kc = 0; kc < 4; ++kc) {
            split2(sc[2 * kc][0],     sc[2 * kc][1],     pah[kc][0], pal[kc][0]);
            split2(sc[2 * kc][2],     sc[2 * kc][3],     pah[kc][1], pal[kc][1]);
            split2(sc[2 * kc + 1][0], sc[2 * kc + 1][1], pah[kc][2], pal[kc][2]);
            split2(sc[2 * kc + 1][2], sc[2 * kc + 1][3], pah[kc][3], pal[kc][3]);
        }

        // ---- O += P V ----
#pragma unroll
        for (int kc = 0; kc < 4; ++kc) {
#pragma unroll
            for (int dg = 0; dg < 4; ++dg) {
                uint32_t vH[4], vL[4];
                const uint32_t voff = (kc * 16 + vrow_) * AP + (dg * 16 + vcol_) * 2;
                ldsm_x4_t(vH, uVh + voff);
                ldsm_x4_t(vL, uVl + voff);
                mma_bf16(oacc[2 * dg],     pah[kc], &vH[0]);
                mma_bf16(oacc[2 * dg + 1], pah[kc], &vH[2]);
                mma_bf16(oacc[2 * dg],     pah[kc], &vL[0]);
                mma_bf16(oacc[2 * dg + 1], pah[kc], &vL[2]);
                mma_bf16(oacc[2 * dg],     pal[kc], &vH[0]);
                mma_bf16(oacc[2 * dg + 1], pal[kc], &vH[2]);
            }
        }
    }

    // ---- epilogue: normalize, write ctx as bf16 hi/lo ----
    const float inv0 = 1.f / l0, inv1 = 1.f / l1;
    const int r0 = wbase + (lane >> 2);
    const int colb = h * HDIM + 2 * (lane & 3);
    const size_t ro0 = (size_t)(b_ * SEQ + r0) * HID + colb;
    const size_t ro1 = ro0 + (size_t)8 * HID;
#pragma unroll
    for (int g = 0; g < 8; ++g) {
        uint32_t hi, lo;
        split2(oacc[g][0] * inv0, oacc[g][1] * inv0, hi, lo);
        *(uint32_t*)(g_chi + ro0 + 8 * g) = hi;
        *(uint32_t*)(g_clo + ro0 + 8 * g) = lo;
        split2(oacc[g][2] * inv1, oacc[g][3] * inv1, hi, lo);
        *(uint32_t*)(g_chi + ro1 + 8 * g) = hi;
        *(uint32_t*)(g_clo + ro1 + 8 * g) = lo;
    }
}

// ---------------------------------------------------------------------------
extern "C" void kernel_launch(void* const* d_in, const int* in_sizes, int n_in,
                              void* d_out, int out_size)
{
    const float* X    = (const float*)d_in[0];
    const int*   pos  = (const int*)  d_in[2];
    const float* cosb = (const float*)d_in[3];
    const float* sinb = (const float*)d_in[4];
    const float* Wq   = (const float*)d_in[5];
    const float* Wk   = (const float*)d_in[6];
    const float* Wv   = (const float*)d_in[7];
    const float* Wo   = (const float*)d_in[8];
    float* out = (float*)d_out;

    __nv_bfloat16 *xhi, *xlo, *chi, *clo;
    cudaGetSymbolAddress((void**)&xhi, g_xhi);
    cudaGetSymbolAddress((void**)&xlo, g_xlo);
    cudaGetSymbolAddress((void**)&chi, g_chi);
    cudaGetSymbolAddress((void**)&clo, g_clo);

    // 1) convert inputs to bf16 hi/lo
    {
        int n8 = BATCH * SEQ * HID / 8;
        split_rows_kernel<<<(n8 + 255) / 256, 256>>>(X, xhi, xlo, n8);
        dim3 gw(HID / 32, HID / 32, 4);
        split_wT_kernel<<<gw, dim3(32, 8)>>>(Wq, Wk, Wv, Wo);
    }
    // 2) QKV projection + RoPE (HMMA) -> bf16 hi/lo Q,K,V
    {
        dim3 g(HID / 128, (BATCH * SEQ) / 128, 3);
        hgemm_kernel<<<g, 256>>>(xhi, xlo, 0, pos, cosb, sinb, nullptr);
    }
    // 3) attention (HMMA flash) -> ctx bf16 hi/lo
    {
        dim3 g(SEQ / 128, NHEAD, BATCH);
        attn_kernel<<<g, 256>>>();
    }
    // 4) output projection (HMMA)
    {
        dim3 g(HID / 128, (BATCH * SEQ) / 128, 1);
        hgemm_kernel<<<g, 256>>>(chi, clo, 1, pos, cosb, sinb, out);
    }
}

// round 5
// speedup vs baseline: 3.2155x; 1.1068x over previous
#include <cuda_runtime.h>
#include <cuda_bf16.h>
#include <cstdint>

#define BATCH 2
#define SEQ   2048
#define HID   1024
#define NHEAD 16
#define HDIM  64
#define SCALE 0.125f

// ---------------- device scratch (static allocations only) ----------------
__device__ __nv_bfloat16 g_xhi[BATCH * SEQ * HID];
__device__ __nv_bfloat16 g_xlo[BATCH * SEQ * HID];
__device__ __nv_bfloat16 g_whi[4 * HID * HID];   // transposed [N][K], mats q,k,v,o
__device__ __nv_bfloat16 g_wlo[4 * HID * HID];
__device__ __nv_bfloat16 g_chi[BATCH * SEQ * HID];
__device__ __nv_bfloat16 g_clo[BATCH * SEQ * HID];
__device__ __nv_bfloat16 g_qhi[BATCH * NHEAD * SEQ * HDIM];
__device__ __nv_bfloat16 g_qlo[BATCH * NHEAD * SEQ * HDIM];
__device__ __nv_bfloat16 g_khi[BATCH * NHEAD * SEQ * HDIM];
__device__ __nv_bfloat16 g_klo[BATCH * NHEAD * SEQ * HDIM];
__device__ __nv_bfloat16 g_vhi[BATCH * NHEAD * SEQ * HDIM];
__device__ __nv_bfloat16 g_vlo[BATCH * NHEAD * SEQ * HDIM];

// ---------------- helpers ----------------
__device__ __forceinline__ uint32_t smem_u32(const void* p) {
    uint32_t a;
    asm("{ .reg .u64 t; cvta.to.shared.u64 t, %1; cvt.u32.u64 %0, t; }" : "=r"(a) : "l"(p));
    return a;
}
__device__ __forceinline__ void ldsm_x4(uint32_t* r, uint32_t addr) {
    asm volatile("ldmatrix.sync.aligned.m8n8.x4.shared.b16 {%0,%1,%2,%3}, [%4];"
                 : "=r"(r[0]), "=r"(r[1]), "=r"(r[2]), "=r"(r[3]) : "r"(addr));
}
__device__ __forceinline__ void ldsm_x4_t(uint32_t* r, uint32_t addr) {
    asm volatile("ldmatrix.sync.aligned.m8n8.x4.trans.shared.b16 {%0,%1,%2,%3}, [%4];"
                 : "=r"(r[0]), "=r"(r[1]), "=r"(r[2]), "=r"(r[3]) : "r"(addr));
}
__device__ __forceinline__ void mma_bf16(float* c, const uint32_t* a, const uint32_t* b) {
    asm volatile(
        "mma.sync.aligned.m16n8k16.row.col.f32.bf16.bf16.f32 "
        "{%0,%1,%2,%3},{%4,%5,%6,%7},{%8,%9},{%0,%1,%2,%3};"
        : "+f"(c[0]), "+f"(c[1]), "+f"(c[2]), "+f"(c[3])
        : "r"(a[0]), "r"(a[1]), "r"(a[2]), "r"(a[3]), "r"(b[0]), "r"(b[1]));
}
__device__ __forceinline__ void split2(float a, float b, uint32_t& hi, uint32_t& lo) {
    __nv_bfloat162 h = __floats2bfloat162_rn(a, b);
    float2 hf = __bfloat1622float2(h);
    __nv_bfloat162 l = __floats2bfloat162_rn(a - hf.x, b - hf.y);
    hi = *(uint32_t*)&h;
    lo = *(uint32_t*)&l;
}
__device__ __forceinline__ void cp16(uint32_t dst, const void* src) {
    asm volatile("cp.async.cg.shared.global [%0], [%1], 16;" :: "r"(dst), "l"(src));
}
#define CP_COMMIT() asm volatile("cp.async.commit_group;" ::: "memory")
#define CP_WAIT0()  asm volatile("cp.async.wait_group 0;" ::: "memory")
#define CP_WAIT1()  asm volatile("cp.async.wait_group 1;" ::: "memory")

// ---------------- convert kernels ----------------
union BPack { __nv_bfloat16 b[8]; uint4 v; };

__global__ void split_rows_kernel(const float* __restrict__ in,
                                  __nv_bfloat16* __restrict__ hi,
                                  __nv_bfloat16* __restrict__ lo, int n8) {
    int i = blockIdx.x * blockDim.x + threadIdx.x;
    if (i >= n8) return;
    float f[8];
    *(float4*)(f)     = ((const float4*)in)[i * 2];
    *(float4*)(f + 4) = ((const float4*)in)[i * 2 + 1];
    BPack h, l;
#pragma unroll
    for (int j = 0; j < 8; ++j) {
        h.b[j] = __float2bfloat16(f[j]);
        l.b[j] = __float2bfloat16(f[j] - __bfloat162float(h.b[j]));
    }
    ((uint4*)hi)[i] = h.v;
    ((uint4*)lo)[i] = l.v;
}

__global__ void split_wT_kernel(const float* __restrict__ Wq, const float* __restrict__ Wk,
                                const float* __restrict__ Wv, const float* __restrict__ Wo) {
    __shared__ float t[32][33];
    const int mat = blockIdx.z;
    const float* W = (mat == 0) ? Wq : (mat == 1) ? Wk : (mat == 2) ? Wv : Wo;
    __nv_bfloat16* hi = g_whi + (size_t)mat * HID * HID;
    __nv_bfloat16* lo = g_wlo + (size_t)mat * HID * HID;
    const int n0 = blockIdx.x * 32, k0 = blockIdx.y * 32;
    const int tx = threadIdx.x, ty = threadIdx.y;
#pragma unroll
    for (int i = 0; i < 4; ++i)
        t[ty + 8 * i][tx] = W[(size_t)(k0 + ty + 8 * i) * HID + n0 + tx];
    __syncthreads();
#pragma unroll
    for (int i = 0; i < 4; ++i) {
        float v = t[tx][ty + 8 * i];
        __nv_bfloat16 h = __float2bfloat16(v);
        size_t idx = (size_t)(n0 + ty + 8 * i) * HID + k0 + tx;
        hi[idx] = h;
        lo[idx] = __float2bfloat16(v - __bfloat162float(h));
    }
}

// ---------------------------------------------------------------------------
// HMMA bf16 split GEMM, 2-stage cp.async pipeline.
// 128x128 CTA tile, BK=32, 8 warps (4 M x 2 N).
// Dynamic smem: 2 stages x 4 tiles x 10240B = 81920B.
// ---------------------------------------------------------------------------
#define TILEB 10240   // 128 rows * 80 bytes

__global__ __launch_bounds__(256, 2) void hgemm_kernel(
    const __nv_bfloat16* __restrict__ Ahi, const __nv_bfloat16* __restrict__ Alo,
    int mode, const int* __restrict__ pos_ids,
    const float* __restrict__ cosb, const float* __restrict__ sinb,
    float* __restrict__ outp)
{
    extern __shared__ char dsm[];
    const uint32_t S0 = smem_u32(dsm);

    const int tid = threadIdx.x;
    const int lane = tid & 31, wid = tid >> 5;
    const int wm = wid & 3, wn = wid >> 2;
    const int z = blockIdx.z;
    const int row0 = blockIdx.y << 7, col0 = blockIdx.x << 7;
    const int wsel = (mode == 0) ? z : 3;
    const __nv_bfloat16* Bhi = g_whi + (size_t)wsel * HID * HID;
    const __nv_bfloat16* Blo = g_wlo + (size_t)wsel * HID * HID;

    float acc[2][8][4];
#pragma unroll
    for (int t = 0; t < 2; ++t)
#pragma unroll
        for (int j = 0; j < 8; ++j)
#pragma unroll
            for (int e = 0; e < 4; ++e) acc[t][j][e] = 0.f;

    const int lrow = tid >> 1;
    const int lch  = (tid & 1) * 2;
    const uint32_t s_off = lrow * 80 + lch * 16;

    const int a_row = wm * 32 + (lane & 15);
    const int a_ch  = lane >> 4;
    const int b_row = wn * 64 + (lane & 7) + ((lane & 16) >> 1);
    const int b_ch  = (lane >> 3) & 1;

    auto stage_load = [&](int it, int s) {
        const int k0 = it * 32;
        const size_t ga = (size_t)(row0 + lrow) * HID + k0 + lch * 8;
        const size_t gb = (size_t)(col0 + lrow) * HID + k0 + lch * 8;
        const uint32_t d = S0 + s * (4 * TILEB) + s_off;
        cp16(d,                 Ahi + ga); cp16(d + 16,             Ahi + ga + 8);
        cp16(d + TILEB,         Alo + ga); cp16(d + TILEB + 16,     Alo + ga + 8);
        cp16(d + 2 * TILEB,     Bhi + gb); cp16(d + 2 * TILEB + 16, Bhi + gb + 8);
        cp16(d + 3 * TILEB,     Blo + gb); cp16(d + 3 * TILEB + 16, Blo + gb + 8);
    };

    stage_load(0, 0);
    CP_COMMIT();

    for (int it = 0; it < HID / 32; ++it) {
        const int s = it & 1;
        if (it + 1 < HID / 32) {
            stage_load(it + 1, s ^ 1);
            CP_COMMIT();
            CP_WAIT1();
        } else {
            CP_WAIT0();
        }
        __syncthreads();

        const uint32_t uAh = S0 + s * (4 * TILEB);
        const uint32_t uAl = uAh + TILEB;
        const uint32_t uBh = uAh + 2 * TILEB;
        const uint32_t uBl = uAh + 3 * TILEB;
#pragma unroll
        for (int kh = 0; kh < 2; ++kh) {
            uint32_t aH[2][4], aL[2][4], bH[4][4], bL[4][4];
            const uint32_t a_off = a_row * 80 + (kh * 2 + a_ch) * 16;
            const uint32_t b_off = b_row * 80 + (kh * 2 + b_ch) * 16;
            ldsm_x4(aH[0], uAh + a_off);
            ldsm_x4(aH[1], uAh + a_off + 16 * 80);
            ldsm_x4(aL[0], uAl + a_off);
            ldsm_x4(aL[1], uAl + a_off + 16 * 80);
#pragma unroll
            for (int g = 0; g < 4; ++g) {
                ldsm_x4(bH[g], uBh + b_off + g * (16 * 80));
                ldsm_x4(bL[g], uBl + b_off + g * (16 * 80));
            }
#pragma unroll
            for (int t = 0; t < 2; ++t)
#pragma unroll
                for (int g = 0; g < 4; ++g) {
                    mma_bf16(acc[t][2 * g],     aH[t], &bH[g][0]);
                    mma_bf16(acc[t][2 * g + 1], aH[t], &bH[g][2]);
                    mma_bf16(acc[t][2 * g],     aH[t], &bL[g][0]);
                    mma_bf16(acc[t][2 * g + 1], aH[t], &bL[g][2]);
                    mma_bf16(acc[t][2 * g],     aL[t], &bH[g][0]);
                    mma_bf16(acc[t][2 * g + 1], aL[t], &bH[g][2]);
                }
        }
        __syncthreads();
    }

    // ---------------- epilogue ----------------
    const int q2 = (lane & 3) * 2;
#pragma unroll
    for (int t = 0; t < 2; ++t) {
#pragma unroll
        for (int h2 = 0; h2 < 2; ++h2) {
            const int row = row0 + wm * 32 + t * 16 + (lane >> 2) + h2 * 8;
            if (mode == 1) {
                float* dst = outp + (size_t)row * HID + col0 + wn * 64 + q2;
#pragma unroll
                for (int j = 0; j < 8; ++j)
                    *(float2*)(dst + j * 8) =
                        make_float2(acc[t][j][h2 * 2], acc[t][j][h2 * 2 + 1]);
            } else {
                const int b_ = row >> 11, s_ = row & (SEQ - 1);
                const int h = (col0 >> 6) + wn;
                const size_t base = ((size_t)(b_ * NHEAD + h) * SEQ + s_) * HDIM;
                if (z == 2) {
#pragma unroll
                    for (int j = 0; j < 8; ++j) {
                        uint32_t hi, lo;
                        split2(acc[t][j][h2 * 2], acc[t][j][h2 * 2 + 1], hi, lo);
                        *(uint32_t*)(g_vhi + base + j * 8 + q2) = hi;
                        *(uint32_t*)(g_vlo + base + j * 8 + q2) = lo;
                    }
                } else {
                    const int pos = pos_ids[b_ * SEQ + s_];
                    const float* cr = cosb + pos * HDIM;
                    const float* sr = sinb + pos * HDIM;
                    __nv_bfloat16* dhi = (z == 0) ? g_qhi : g_khi;
                    __nv_bfloat16* dlo = (z == 0) ? g_qlo : g_klo;
                    const float sc_ = (z == 0) ? SCALE : 1.0f;
#pragma unroll
                    for (int j = 0; j < 4; ++j) {
                        float o1[2], o2[2];
#pragma unroll
                        for (int e = 0; e < 2; ++e) {
                            const int d = j * 8 + q2 + e;
                            const float x = acc[t][j][h2 * 2 + e];
                            const float y = acc[t][j + 4][h2 * 2 + e];
                            o1[e] = (x * cr[d] - y * sr[d]) * sc_;
                            o2[e] = (y * cr[d + 32] + x * sr[d + 32]) * sc_;
                        }
                        uint32_t hi, lo;
                        split2(o1[0], o1[1], hi, lo);
                        *(uint32_t*)(dhi + base + j * 8 + q2) = hi;
                        *(uint32_t*)(dlo + base + j * 8 + q2) = lo;
                        split2(o2[0], o2[1], hi, lo);
                        *(uint32_t*)(dhi + base + j * 8 + q2 + 32) = hi;
                        *(uint32_t*)(dlo + base + j * 8 + q2 + 32) = lo;
                    }
                }
            }
        }
    }
}

// ---------------------------------------------------------------------------
// HMMA flash attention, 2-stage cp.async pipeline.
// 128 q x 64 kv per tile, 8 warps x 16 q rows; analytic causal mask.
// Dynamic smem: 2 stages x 4 bufs x 9216B = 73728B.
// ---------------------------------------------------------------------------
#define AP  144    // bytes per smem row (64 bf16 + pad)
#define KT_ 9216   // 64 rows * AP

__global__ __launch_bounds__(256) void attn_kernel()
{
    extern __shared__ char dsm[];
    const uint32_t S0 = smem_u32(dsm);

    const int tid = threadIdx.x, lane = tid & 31, wid = tid >> 5;
    const int qi = gridDim.x - 1 - blockIdx.x;
    const int h = blockIdx.y, b_ = blockIdx.z;
    const int q0 = qi << 7;
    const size_t hb = (size_t)(b_ * NHEAD + h) * SEQ * HDIM;
    const __nv_bfloat16 *qhi = g_qhi + hb, *qlo = g_qlo + hb;
    const __nv_bfloat16 *khi = g_khi + hb, *klo = g_klo + hb;
    const __nv_bfloat16 *vhi = g_vhi + hb, *vlo = g_vlo + hb;

    // ---- stage Q into stage-0 buffers via cp.async ----
    {
        const int r = tid >> 1, half = tid & 1;
        const __nv_bfloat16* sh = qhi + (size_t)(q0 + r) * HDIM + half * 32;
        const __nv_bfloat16* sl = qlo + (size_t)(q0 + r) * HDIM + half * 32;
        const uint32_t dh = S0 + ((r < 64) ? 0 : 2 * KT_) + (r & 63) * AP + half * 64;
        const uint32_t dl = dh + KT_;
#pragma unroll
        for (int c = 0; c < 4; ++c) {
            cp16(dh + c * 16, sh + c * 8);
            cp16(dl + c * 16, sl + c * 8);
        }
    }
    CP_COMMIT();
    CP_WAIT0();
    __syncthreads();

    // ---- Q fragments ----
    uint32_t qfh[4][4], qfl[4][4];
    {
        const uint32_t bh = S0 + ((wid < 4) ? 0 : 2 * KT_);
        const uint32_t bl = bh + KT_;
        const int arow = (wid & 3) * 16 + (lane & 15);
        const int ach = lane >> 4;
#pragma unroll
        for (int kc = 0; kc < 4; ++kc) {
            const uint32_t off = arow * AP + (kc * 2 + ach) * 16;
            ldsm_x4(qfh[kc], bh + off);
            ldsm_x4(qfl[kc], bl + off);
        }
    }
    __syncthreads();

    float oacc[8][4];
#pragma unroll
    for (int g = 0; g < 8; ++g)
#pragma unroll
        for (int e = 0; e < 4; ++e) oacc[g][e] = 0.f;
    float m0 = -1e30f, m1 = -1e30f, l0 = 0.f, l1 = 0.f;

    const int wbase = q0 + wid * 16;
    const int nt = (q0 >> 6) + 2;
    const int lrow = tid >> 2, lq = tid & 3;
    const int brow_ = (lane & 7) + ((lane & 16) >> 1);
    const int bch_ = (lane >> 3) & 1;
    const int vrow_ = lane & 15;
    const int vcol_ = (lane & 16) ? 8 : 0;

    auto kv_load = [&](int kt, int s) {
        const int k0 = kt << 6;
        const size_t src = (size_t)(k0 + lrow) * HDIM + lq * 16;
        const uint32_t d = S0 + s * (4 * KT_) + lrow * AP + lq * 32;
        cp16(d,                khi + src); cp16(d + 16,            khi + src + 8);
        cp16(d + KT_,          klo + src); cp16(d + KT_ + 16,      klo + src + 8);
        cp16(d + 2 * KT_,      vhi + src); cp16(d + 2 * KT_ + 16,  vhi + src + 8);
        cp16(d + 3 * KT_,      vlo + src); cp16(d + 3 * KT_ + 16,  vlo + src + 8);
    };

    kv_load(0, 0);
    CP_COMMIT();

    for (int kt = 0; kt < nt; ++kt) {
        const int k0 = kt << 6;
        const int s = kt & 1;
        if (kt + 1 < nt) {
            kv_load(kt + 1, s ^ 1);
            CP_COMMIT();
            CP_WAIT1();
        } else {
            CP_WAIT0();
        }
        __syncthreads();

        if (k0 <= wbase + 15) {
            const uint32_t uKh = S0 + s * (4 * KT_);
            const uint32_t uKl = uKh + KT_;
            const uint32_t uVh = uKh + 2 * KT_;
            const uint32_t uVl = uKh + 3 * KT_;

            // ---- S = Q K^T ----
            float sc[8][4];
#pragma unroll
            for (int g = 0; g < 8; ++g)
#pragma unroll
                for (int e = 0; e < 4; ++e) sc[g][e] = 0.f;
#pragma unroll
            for (int kc = 0; kc < 4; ++kc) {
#pragma unroll
                for (int g = 0; g < 4; ++g) {
                    uint32_t bH[4], bL[4];
                    const uint32_t boff = (g * 16 + brow_) * AP + (kc * 2 + bch_) * 16;
                    ldsm_x4(bH, uKh + boff);
                    ldsm_x4(bL, uKl + boff);
                    mma_bf16(sc[2 * g],     qfh[kc], &bH[0]);
                    mma_bf16(sc[2 * g + 1], qfh[kc], &bH[2]);
                    mma_bf16(sc[2 * g],     qfh[kc], &bL[0]);
                    mma_bf16(sc[2 * g + 1], qfh[kc], &bL[2]);
                    mma_bf16(sc[2 * g],     qfl[kc], &bH[0]);
                    mma_bf16(sc[2 * g + 1], qfl[kc], &bH[2]);
                }
            }

            // ---- causal mask ----
            const int r0 = wbase + (lane >> 2), r1 = r0 + 8;
            if (k0 + 63 > wbase) {
#pragma unroll
                for (int g = 0; g < 8; ++g) {
#pragma unroll
                    for (int e = 0; e < 2; ++e) {
                        const int col = k0 + 8 * g + 2 * (lane & 3) + e;
                        if (col > r0) sc[g][e] = -1e9f;
                        if (col > r1) sc[g][2 + e] = -1e9f;
                    }
                }
            }

            // ---- online softmax ----
            float mx0 = sc[0][0], mx1 = sc[0][2];
#pragma unroll
            for (int g = 0; g < 8; ++g) {
                mx0 = fmaxf(mx0, fmaxf(sc[g][0], sc[g][1]));
                mx1 = fmaxf(mx1, fmaxf(sc[g][2], sc[g][3]));
            }
            mx0 = fmaxf(mx0, __shfl_xor_sync(0xffffffffu, mx0, 1));
            mx0 = fmaxf(mx0, __shfl_xor_sync(0xffffffffu, mx0, 2));
            mx1 = fmaxf(mx1, __shfl_xor_sync(0xffffffffu, mx1, 1));
            mx1 = fmaxf(mx1, __shfl_xor_sync(0xffffffffu, mx1, 2));
            const float nm0 = fmaxf(m0, mx0), nm1 = fmaxf(m1, mx1);
            const float cr0 = __expf(m0 - nm0), cr1 = __expf(m1 - nm1);
            m0 = nm0; m1 = nm1;
            float rs0 = 0.f, rs1 = 0.f;
#pragma unroll
            for (int g = 0; g < 8; ++g) {
                sc[g][0] = __expf(sc[g][0] - nm0);
                sc[g][1] = __expf(sc[g][1] - nm0);
                sc[g][2] = __expf(sc[g][2] - nm1);
                sc[g][3] = __expf(sc[g][3] - nm1);
                rs0 += sc[g][0] + sc[g][1];
                rs1 += sc[g][2] + sc[g][3];
            }
            rs0 += __shfl_xor_sync(0xffffffffu, rs0, 1);
            rs0 += __shfl_xor_sync(0xffffffffu, rs0, 2);
            rs1 += __shfl_xor_sync(0xffffffffu, rs1, 1);
            rs1 += __shfl_xor_sync(0xffffffffu, rs1, 2);
            l0 = l0 * cr0 + rs0;
            l1 = l1 * cr1 + rs1;
#pragma unroll
            for (int g = 0; g < 8; ++g) {
                oacc[g][0] *= cr0; oacc[g][1] *= cr0;
                oacc[g][2] *= cr1; oacc[g][3] *= cr1;
            }

            // ---- P fragments (hi/lo) ----
            uint32_t pah[4][4], pal[4][4];
#pragma unroll
            for (int kc = 0; kc < 4; ++kc) {
                split2(sc[2 * kc][0],     sc[2 * kc][1],     pah[kc][0], pal[kc][0]);
                split2(sc[2 * kc][2],     sc[2 * kc][3],     pah[kc][1], pal[kc][1]);
                split2(sc[2 * kc + 1][0], sc[2 * kc + 1][1], pah[kc][2], pal[kc][2]);
                split2(sc[2 * kc + 1][2], sc[2 * kc + 1][3], pah[kc][3], pal[kc][3]);
            }

            // ---- O += P V ----
#pragma unroll
            for (int kc = 0; kc < 4; ++kc) {
#pragma unroll
                for (int dg = 0; dg < 4; ++dg) {
                    uint32_t vH[4], vL[4];
                    const uint32_t voff = (kc * 16 + vrow_) * AP + (dg * 16 + vcol_) * 2;
                    ldsm_x4_t(vH, uVh + voff);
                    ldsm_x4_t(vL, uVl + voff);
                    mma_bf16(oacc[2 * dg],     pah[kc], &vH[0]);
                    mma_bf16(oacc[2 * dg + 1], pah[kc], &vH[2]);
                    mma_bf16(oacc[2 * dg],     pah[kc], &vL[0]);
                    mma_bf16(oacc[2 * dg + 1], pah[kc], &vL[2]);
                    mma_bf16(oacc[2 * dg],     pal[kc], &vH[0]);
                    mma_bf16(oacc[2 * dg + 1], pal[kc], &vH[2]);
                }
            }
        }
        __syncthreads();
    }

    // ---- epilogue ----
    const float inv0 = 1.f / l0, inv1 = 1.f / l1;
    const int r0 = wbase + (lane >> 2);
    const int colb = h * HDIM + 2 * (lane & 3);
    const size_t ro0 = (size_t)(b_ * SEQ + r0) * HID + colb;
    const size_t ro1 = ro0 + (size_t)8 * HID;
#pragma unroll
    for (int g = 0; g < 8; ++g) {
        uint32_t hi, lo;
        split2(oacc[g][0] * inv0, oacc[g][1] * inv0, hi, lo);
        *(uint32_t*)(g_chi + ro0 + 8 * g) = hi;
        *(uint32_t*)(g_clo + ro0 + 8 * g) = lo;
        split2(oacc[g][2] * inv1, oacc[g][3] * inv1, hi, lo);
        *(uint32_t*)(g_chi + ro1 + 8 * g) = hi;
        *(uint32_t*)(g_clo + ro1 + 8 * g) = lo;
    }
}

// ---------------------------------------------------------------------------
extern "C" void kernel_launch(void* const* d_in, const int* in_sizes, int n_in,
                              void* d_out, int out_size)
{
    const float* X    = (const float*)d_in[0];
    const int*   pos  = (const int*)  d_in[2];
    const float* cosb = (const float*)d_in[3];
    const float* sinb = (const float*)d_in[4];
    const float* Wq   = (const float*)d_in[5];
    const float* Wk   = (const float*)d_in[6];
    const float* Wv   = (const float*)d_in[7];
    const float* Wo   = (const float*)d_in[8];
    float* out = (float*)d_out;

    static int attr_done = 0;
    if (!attr_done) {
        cudaFuncSetAttribute(hgemm_kernel, cudaFuncAttributeMaxDynamicSharedMemorySize,
                             2 * 4 * TILEB);
        cudaFuncSetAttribute(attn_kernel, cudaFuncAttributeMaxDynamicSharedMemorySize,
                             2 * 4 * KT_);
        attr_done = 1;
    }

    __nv_bfloat16 *xhi, *xlo, *chi, *clo;
    cudaGetSymbolAddress((void**)&xhi, g_xhi);
    cudaGetSymbolAddress((void**)&xlo, g_xlo);
    cudaGetSymbolAddress((void**)&chi, g_chi);
    cudaGetSymbolAddress((void**)&clo, g_clo);

    // 1) convert inputs to bf16 hi/lo
    {
        int n8 = BATCH * SEQ * HID / 8;
        split_rows_kernel<<<(n8 + 255) / 256, 256>>>(X, xhi, xlo, n8);
        dim3 gw(HID / 32, HID / 32, 4);
        split_wT_kernel<<<gw, dim3(32, 8)>>>(Wq, Wk, Wv, Wo);
    }
    // 2) QKV projection + RoPE (HMMA, pipelined)
    {
        dim3 g(HID / 128, (BATCH * SEQ) / 128, 3);
        hgemm_kernel<<<g, 256, 2 * 4 * TILEB>>>(xhi, xlo, 0, pos, cosb, sinb, nullptr);
    }
    // 3) attention (HMMA flash, pipelined)
    {
        dim3 g(SEQ / 128, NHEAD, BATCH);
        attn_kernel<<<g, 256, 2 * 4 * KT_>>>();
    }
    // 4) output projection (HMMA, pipelined)
    {
        dim3 g(HID / 128, (BATCH * SEQ) / 128, 1);
        hgemm_kernel<<<g, 256, 2 * 4 * TILEB>>>(chi, clo, 1, pos, cosb, sinb, out);
    }
}